// round 8
// baseline (speedup 1.0000x reference)
#include <cuda_runtime.h>
#include <cstdint>

typedef uint32_t u32;

// Problem constants
#define BB 2
#define SS 1024
#define HH 8
#define DD 64
#define RR 32
#define KW 128
#define CC (HH*DD)          // 512
#define ZLEN (4*KW+SS)      // 1536
#define TS 64               // s per CTA
#define NTHREADS 128

// SMEM layout
#define ZSTRIDE 200                         // words/row; pair-interleaved, LDS.64 conflict-free
#define Z_BYTES   (RR * ZSTRIDE * 4)        // 25600
#define QKSTRIDE 132
#define QK_BYTES  (DD * QKSTRIDE * 4)       // 33792
#define W_BYTES   (2 * 256 * 4)             // 2048 (zero-padded filters)
#define DYN_BYTES (Z_BYTES + QK_BYTES + W_BYTES)   // 61440

__device__ __forceinline__ u32 cvt_tf32(float x) {
    u32 r; asm("cvt.rna.tf32.f32 %0, %1;" : "=r"(r) : "f"(x)); return r;
}

__device__ __forceinline__ void mma_acc(float* c,
                                        u32 a0, u32 a1, u32 a2, u32 a3,
                                        u32 b0, u32 b1) {
    asm volatile(
        "mma.sync.aligned.m16n8k8.row.col.f32.tf32.tf32.f32 "
        "{%0,%1,%2,%3}, {%4,%5,%6,%7}, {%8,%9}, {%0,%1,%2,%3};"
        : "+f"(c[0]), "+f"(c[1]), "+f"(c[2]), "+f"(c[3])
        : "r"(a0), "r"(a1), "r"(a2), "r"(a3), "r"(b0), "r"(b1));
}
__device__ __forceinline__ void mma_init(float* c,
                                         u32 a0, u32 a1, u32 a2, u32 a3,
                                         u32 b0, u32 b1) {
    asm volatile(
        "mma.sync.aligned.m16n8k8.row.col.f32.tf32.tf32.f32 "
        "{%0,%1,%2,%3}, {%4,%5,%6,%7}, {%8,%9}, {%10,%11,%12,%13};"
        : "=f"(c[0]), "=f"(c[1]), "=f"(c[2]), "=f"(c[3])
        : "r"(a0), "r"(a1), "r"(a2), "r"(a3), "r"(b0), "r"(b1),
          "f"(0.f), "f"(0.f), "f"(0.f), "f"(0.f));
}

__global__ __launch_bounds__(NTHREADS, 3)
void convspe_mma_kernel(const float* __restrict__ qg,
                        const float* __restrict__ kg,
                        const float* __restrict__ wq,
                        const float* __restrict__ wk,
                        const float* __restrict__ zg,
                        float* __restrict__ out)
{
    extern __shared__ char dyn[];
    u32*   Zs   = reinterpret_cast<u32*>(dyn);                        // [32][200] tf32, pair-interleaved
    float* QK   = reinterpret_cast<float*>(dyn + Z_BYTES);            // [64 d][132]: rows 0-63 q, 64-127 k
    float* wpad = reinterpret_cast<float*>(dyn + Z_BYTES + QK_BYTES); // [2][256], band at [64,192)

    const int tid  = threadIdx.x;
    const int w    = tid >> 5;
    const int lane = tid & 31;
    const int g    = lane >> 2;       // row group 0..7
    const int qi   = lane & 3;        // quad index 0..3

    const int stile = blockIdx.x;     // 0..15
    const int h     = blockIdx.y;     // 0..7
    const int b     = blockIdx.z;     // 0..1
    const int s0    = stile * TS;
    const int cbase = h * DD;

    // ---- zero-fill wpad once (out-of-band entries stay 0 forever) ----
    #pragma unroll
    for (int i = 0; i < 4; i++) wpad[tid + i * NTHREADS] = 0.f;

    // ---- stage q/k transposed: QK[d][row], rows 0-63 q, 64-127 k ----
    for (int idx = tid; idx < TS * 16; idx += NTHREADS) {  // 8 iters
        int srow = idx >> 4;
        int c4   = idx & 15;
        int goff = (((b * SS + s0 + srow) * HH + h) * DD) + c4 * 4;
        float4 q4 = *reinterpret_cast<const float4*>(qg + goff);
        float4 k4 = *reinterpret_cast<const float4*>(kg + goff);
        float qa[4] = {q4.x, q4.y, q4.z, q4.w};
        float ka[4] = {k4.x, k4.y, k4.z, k4.w};
        #pragma unroll
        for (int j = 0; j < 4; j++) {
            QK[(c4 * 4 + j) * QKSTRIDE + srow]      = qa[j];
            QK[(c4 * 4 + j) * QKSTRIDE + 64 + srow] = ka[j];
        }
    }

    // ---- per-warp constants: warp owns 2 adjacent m-tiles of one filter half ----
    const int f     = w >> 1;          // 0: qhat (filter wk), 1: khat (filter wq)
    const int half  = w & 1;           // which 32-row block
    const int c0    = half * 4;        // chunk base
    const int fbase = f * 64 + half * 32;
    const float* wp = wpad + f * 256;

    float acc0[4][4], acc1[4][4];      // running d-sums for m-tile0 / m-tile1
    #pragma unroll
    for (int n = 0; n < 4; n++)
        #pragma unroll
        for (int i = 0; i < 4; i++) { acc0[n][i] = 0.f; acc1[n][i] = 0.f; }

    const int qg_off = qi - g;         // lane band offset

    for (int d = 0; d < DD; d++) {
        const int c = cbase + d;

        __syncthreads();   // previous iteration's Zs/wpad consumers done

        // -- stage filters (band [64,192)): row0 = wk (qhat), row1 = wq (khat) --
        wpad[64 + tid]        = wk[c * KW + tid];
        wpad[64 + 256 + tid]  = wq[c * KW + tid];

        // -- stage Z tile (32 x 192) tf32, pair-interleaved (col j, j+4) --
        #pragma unroll
        for (int i = 0; i < 6; i++) {
            int idx  = tid + i * NTHREADS;       // 0..767 = 32 rows x 24 chunks
            int row  = idx / 24;
            int cc   = idx - row * 24;
            const float* p = zg + ((size_t)((b * RR + row) * CC + c)) * ZLEN
                           + KW + s0 + cc * 8;
            float4 z0 = *reinterpret_cast<const float4*>(p);
            float4 z1 = *reinterpret_cast<const float4*>(p + 4);
            u32* dst = Zs + row * ZSTRIDE + cc * 8;
            uint4 o0 = make_uint4(cvt_tf32(z0.x), cvt_tf32(z1.x),
                                  cvt_tf32(z0.y), cvt_tf32(z1.y));
            uint4 o1 = make_uint4(cvt_tf32(z0.z), cvt_tf32(z1.z),
                                  cvt_tf32(z0.w), cvt_tf32(z1.w));
            *reinterpret_cast<uint4*>(dst)     = o0;
            *reinterpret_cast<uint4*>(dst + 4) = o1;
        }
        __syncthreads();

        // -- build unscaled A frags (shared by both m-tiles): aw[i] ~ chunk offset i-3 --
        u32 aw0[21], aw2[21];
        #pragma unroll
        for (int i = 0; i < 21; i++) {
            aw0[i] = cvt_tf32(wp[40 + 8 * i + qg_off]);
            aw2[i] = cvt_tf32(wp[44 + 8 * i + qg_off]);
        }

        // -- per-d conv via MMA: work = W_band x Z (no q scaling) --
        float work0[4][4], work1[4][4];

        #pragma unroll
        for (int u = 0; u < 20; u++) {
            const int kw_ = (c0 + u) * 8 + qi * 2;   // pair word offset
            uint2 bb[4];
            #pragma unroll
            for (int n = 0; n < 4; n++)
                bb[n] = *reinterpret_cast<const uint2*>(
                    Zs + (n * 8 + g) * ZSTRIDE + kw_);

            if (u < 18) {   // m-tile 0: local chunk u
                const u32 a0 = aw0[u + 3], a1 = aw0[u + 2];
                const u32 a2 = aw2[u + 3], a3 = aw2[u + 2];
                if (u == 0) {
                    #pragma unroll
                    for (int n = 0; n < 4; n++)
                        mma_init(work0[n], a0, a1, a2, a3, bb[n].x, bb[n].y);
                } else {
                    #pragma unroll
                    for (int n = 0; n < 4; n++)
                        mma_acc(work0[n], a0, a1, a2, a3, bb[n].x, bb[n].y);
                }
            }
            if (u >= 2) {   // m-tile 1: frags shifted by 2 chunks
                const u32 a0 = aw0[u + 1], a1 = aw0[u];
                const u32 a2 = aw2[u + 1], a3 = aw2[u];
                if (u == 2) {
                    #pragma unroll
                    for (int n = 0; n < 4; n++)
                        mma_init(work1[n], a0, a1, a2, a3, bb[n].x, bb[n].y);
                } else {
                    #pragma unroll
                    for (int n = 0; n < 4; n++)
                        mma_acc(work1[n], a0, a1, a2, a3, bb[n].x, bb[n].y);
                }
            }
        }

        // -- scale by q/k at (s, d) and accumulate over d (exact fp32) --
        const float* qkrow = QK + d * QKSTRIDE + fbase;
        const float qv00 = qkrow[g];
        const float qv01 = qkrow[g + 8];
        const float qv10 = qkrow[g + 16];
        const float qv11 = qkrow[g + 24];
        #pragma unroll
        for (int n = 0; n < 4; n++) {
            acc0[n][0] = fmaf(qv00, work0[n][0], acc0[n][0]);
            acc0[n][1] = fmaf(qv00, work0[n][1], acc0[n][1]);
            acc0[n][2] = fmaf(qv01, work0[n][2], acc0[n][2]);
            acc0[n][3] = fmaf(qv01, work0[n][3], acc0[n][3]);
            acc1[n][0] = fmaf(qv10, work1[n][0], acc1[n][0]);
            acc1[n][1] = fmaf(qv10, work1[n][1], acc1[n][1]);
            acc1[n][2] = fmaf(qv11, work1[n][2], acc1[n][2]);
            acc1[n][3] = fmaf(qv11, work1[n][3], acc1[n][3]);
        }
    }

    // ---- epilogue: write accumulators straight to gmem ----
    const int khat_off = BB * SS * HH * RR;
    float* obase = out + (f ? khat_off : 0);
    #pragma unroll
    for (int mt = 0; mt < 2; mt++) {
        const int srow = half * 32 + mt * 16 + g;
        float* ob  = obase + ((b * SS + s0 + srow) * HH + h) * RR;
        float* ob8 = ob + 8 * HH * RR;     // srow + 8
        #pragma unroll
        for (int n = 0; n < 4; n++) {
            const int col = n * 8 + 2 * qi;
            const float (*acc)[4] = mt ? acc1 : acc0;
            *reinterpret_cast<float2*>(ob  + col) = make_float2(acc[n][0], acc[n][1]);
            *reinterpret_cast<float2*>(ob8 + col) = make_float2(acc[n][2], acc[n][3]);
        }
    }
}

extern "C" void kernel_launch(void* const* d_in, const int* in_sizes, int n_in,
                              void* d_out, int out_size)
{
    const float* queries = (const float*)d_in[0];
    const float* keys    = (const float*)d_in[1];
    const float* wq      = (const float*)d_in[2];
    const float* wk      = (const float*)d_in[3];
    const float* z       = (const float*)d_in[4];
    float* out = (float*)d_out;

    cudaFuncSetAttribute(convspe_mma_kernel,
                         cudaFuncAttributeMaxDynamicSharedMemorySize, DYN_BYTES);

    dim3 grid(SS / TS, HH, BB);   // 16 x 8 x 2 = 256 CTAs
    dim3 block(NTHREADS);
    convspe_mma_kernel<<<grid, block, DYN_BYTES>>>(queries, keys, wq, wk, z, out);
}

// round 9
// speedup vs baseline: 1.2848x; 1.2848x over previous
#include <cuda_runtime.h>
#include <cstdint>

typedef uint32_t u32;

// Problem constants
#define BB 2
#define SS 1024
#define HH 8
#define DD 64
#define RR 32
#define KW 128
#define CC (HH*DD)          // 512
#define ZLEN (4*KW+SS)      // 1536
#define TS 64               // s per CTA
#define NTHREADS 128
#define DSPLIT 4            // d-reduction split across CTAs
#define DLOC (DD/DSPLIT)    // 16 d per CTA

#define OUTN (BB*SS*HH*RR*2)   // 1,048,576 floats (qhat+khat)

// partial sums for dh = 1..3
__device__ float g_part[3][OUTN];

// SMEM layout
#define ZSTRIDE 196                         // words/row (conflict-free, 16B-aligned)
#define Z_BYTES   (RR * ZSTRIDE * 4)        // 25088
#define QKSTRIDE 132
#define QK_BYTES  (DLOC * QKSTRIDE * 4)     // 8448
#define W_BYTES   (2 * 256 * 4)             // 2048 (zero-padded filters)
#define DYN_BYTES (Z_BYTES + QK_BYTES + W_BYTES)   // 35584

__device__ __forceinline__ u32 cvt_tf32(float x) {
    u32 r; asm("cvt.rna.tf32.f32 %0, %1;" : "=r"(r) : "f"(x)); return r;
}

__device__ __forceinline__ void mma_tf32(float* c,
                                         u32 a0, u32 a1, u32 a2, u32 a3,
                                         u32 b0, u32 b1) {
    asm volatile(
        "mma.sync.aligned.m16n8k8.row.col.f32.tf32.tf32.f32 "
        "{%0,%1,%2,%3}, {%4,%5,%6,%7}, {%8,%9}, {%0,%1,%2,%3};"
        : "+f"(c[0]), "+f"(c[1]), "+f"(c[2]), "+f"(c[3])
        : "r"(a0), "r"(a1), "r"(a2), "r"(a3), "r"(b0), "r"(b1));
}

__global__ __launch_bounds__(NTHREADS, 3)
void convspe_mma_kernel(const float* __restrict__ qg,
                        const float* __restrict__ kg,
                        const float* __restrict__ wq,
                        const float* __restrict__ wk,
                        const float* __restrict__ zg,
                        float* __restrict__ out)
{
    extern __shared__ char dyn[];
    u32*   Zs   = reinterpret_cast<u32*>(dyn);                       // [32][196] tf32
    float* QK   = reinterpret_cast<float*>(dyn + Z_BYTES);           // [16 dl][132]: 0-63 q, 64-127 k
    float* wpad = reinterpret_cast<float*>(dyn + Z_BYTES + QK_BYTES);// [2][256], band at [64,192)

    const int tid  = threadIdx.x;
    const int w    = tid >> 5;
    const int lane = tid & 31;
    const int g    = lane >> 2;       // row group 0..7
    const int qi   = lane & 3;        // quad index 0..3

    const int stile = blockIdx.x;     // 0..15
    const int h     = blockIdx.y;     // 0..7
    const int bz    = blockIdx.z;     // 0..7
    const int b     = bz >> 2;
    const int dh    = bz & 3;         // d-split index
    const int dbase = dh * DLOC;
    const int s0    = stile * TS;
    const int cbase = h * DD + dbase;

    // ---- zero-fill wpad once (out-of-band entries stay 0 forever) ----
    #pragma unroll
    for (int i = 0; i < 4; i++) wpad[tid + i * NTHREADS] = 0.f;

    // ---- stage q/k transposed for this CTA's 16 d's: QK[dl][row] ----
    for (int idx = tid; idx < TS * 4; idx += NTHREADS) {  // 2 iters
        int srow = idx >> 2;
        int c4   = idx & 3;           // 0..3 (4 floats each -> dl 0..15)
        int goff = (((b * SS + s0 + srow) * HH + h) * DD) + dbase + c4 * 4;
        float4 q4 = *reinterpret_cast<const float4*>(qg + goff);
        float4 k4 = *reinterpret_cast<const float4*>(kg + goff);
        float qa[4] = {q4.x, q4.y, q4.z, q4.w};
        float ka[4] = {k4.x, k4.y, k4.z, k4.w};
        #pragma unroll
        for (int j = 0; j < 4; j++) {
            QK[(c4 * 4 + j) * QKSTRIDE + srow]      = qa[j];
            QK[(c4 * 4 + j) * QKSTRIDE + 64 + srow] = ka[j];
        }
    }

    // ---- per-warp constants (R6 structure): warp owns 2 m-tiles of one filter ----
    const int f      = w >> 1;          // 0: qhat rows (filter wk), 1: khat rows (filter wq)
    const int c0     = (w & 1) * 4;     // chunk base
    const int m_base = w * 32;          // warp's first M row

    float acc[2][4][4];
    #pragma unroll
    for (int t = 0; t < 2; t++)
        #pragma unroll
        for (int n = 0; n < 4; n++)
            #pragma unroll
            for (int i = 0; i < 4; i++) acc[t][n][i] = 0.f;

    const float* wp = wpad + f * 256;

    for (int d = 0; d < DLOC; d++) {
        const int c = cbase + d;

        __syncthreads();   // previous iteration's readers done (also covers init stores)

        // -- stage filters into band region [64,192) --
        wpad[64 + tid]       = wk[c * KW + tid];
        wpad[256 + 64 + tid] = wq[c * KW + tid];

        // -- stage Z tile (32 x 192), tf32-rounded --
        #pragma unroll
        for (int i = 0; i < 12; i++) {
            int idx  = tid + i * NTHREADS;       // 0..1535
            int zrow = idx / 48;
            int gq   = idx - zrow * 48;
            float4 v = *reinterpret_cast<const float4*>(
                zg + ((size_t)((b * RR + zrow) * CC + c)) * ZLEN + KW + s0 + gq * 4);
            uint4 o;
            o.x = cvt_tf32(v.x); o.y = cvt_tf32(v.y);
            o.z = cvt_tf32(v.z); o.w = cvt_tf32(v.w);
            *reinterpret_cast<uint4*>(Zs + zrow * ZSTRIDE + gq * 4) = o;
        }
        __syncthreads();

        // -- per-d A-row scalars --
        float qv00 = QK[d * QKSTRIDE + m_base + g];
        float qv01 = QK[d * QKSTRIDE + m_base + g + 8];
        float qv10 = QK[d * QKSTRIDE + m_base + 16 + g];
        float qv11 = QK[d * QKSTRIDE + m_base + 16 + g + 8];

        // -- 20 union chunks; m-tile0 active u<18, m-tile1 active u>=2 --
        #pragma unroll
        for (int u = 0; u < 20; u++) {
            const int kg = (c0 + u) * 8 + qi;

            u32 b0[4], b1[4];
            #pragma unroll
            for (int n = 0; n < 4; n++) {
                const u32* zr = Zs + (n * 8 + g) * ZSTRIDE + kg;
                b0[n] = zr[0];
                b1[n] = zr[4];
            }

            if (u < 18) {   // m-tile 0
                int wi = 64 + 8 * u + qi - g;
                u32 a0 = cvt_tf32(qv00 * wp[wi]);
                u32 a2 = cvt_tf32(qv00 * wp[wi + 4]);
                u32 a1 = cvt_tf32(qv01 * wp[wi - 8]);
                u32 a3 = cvt_tf32(qv01 * wp[wi - 4]);
                #pragma unroll
                for (int n = 0; n < 4; n++)
                    mma_tf32(acc[0][n], a0, a1, a2, a3, b0[n], b1[n]);
            }
            if (u >= 2) {   // m-tile 1
                int wi = 64 + 8 * u + qi - g - 16;
                u32 a0 = cvt_tf32(qv10 * wp[wi]);
                u32 a2 = cvt_tf32(qv10 * wp[wi + 4]);
                u32 a1 = cvt_tf32(qv11 * wp[wi - 8]);
                u32 a3 = cvt_tf32(qv11 * wp[wi - 4]);
                #pragma unroll
                for (int n = 0; n < 4; n++)
                    mma_tf32(acc[1][n], a0, a1, a2, a3, b0[n], b1[n]);
            }
        }
    }

    // ---- epilogue: dh==0 writes out directly, others write partial scratch ----
    float* obase0 = (dh == 0) ? out : g_part[dh - 1];
    const int khat_off = BB * SS * HH * RR;
    #pragma unroll
    for (int t = 0; t < 2; t++) {
        int row  = m_base + 16 * t + g;
        int srow = row & 63;
        float* ob  = obase0 + (f ? khat_off : 0)
                   + ((b * SS + s0 + srow) * HH + h) * RR;
        float* ob8 = ob + 8 * HH * RR;  // srow + 8
        #pragma unroll
        for (int n = 0; n < 4; n++) {
            int col = n * 8 + 2 * qi;
            *reinterpret_cast<float2*>(ob  + col) = make_float2(acc[t][n][0], acc[t][n][1]);
            *reinterpret_cast<float2*>(ob8 + col) = make_float2(acc[t][n][2], acc[t][n][3]);
        }
    }
}

// deterministic combine: out += part0 + part1 + part2
__global__ __launch_bounds__(256)
void convspe_combine_kernel(float* __restrict__ out)
{
    int i = blockIdx.x * blockDim.x + threadIdx.x;   // float4 index
    if (i >= OUTN / 4) return;
    float4 o  = reinterpret_cast<float4*>(out)[i];
    float4 p0 = reinterpret_cast<const float4*>(g_part[0])[i];
    float4 p1 = reinterpret_cast<const float4*>(g_part[1])[i];
    float4 p2 = reinterpret_cast<const float4*>(g_part[2])[i];
    o.x += p0.x + p1.x + p2.x;
    o.y += p0.y + p1.y + p2.y;
    o.z += p0.z + p1.z + p2.z;
    o.w += p0.w + p1.w + p2.w;
    reinterpret_cast<float4*>(out)[i] = o;
}

extern "C" void kernel_launch(void* const* d_in, const int* in_sizes, int n_in,
                              void* d_out, int out_size)
{
    const float* queries = (const float*)d_in[0];
    const float* keys    = (const float*)d_in[1];
    const float* wq      = (const float*)d_in[2];
    const float* wk      = (const float*)d_in[3];
    const float* z       = (const float*)d_in[4];
    float* out = (float*)d_out;

    cudaFuncSetAttribute(convspe_mma_kernel,
                         cudaFuncAttributeMaxDynamicSharedMemorySize, DYN_BYTES);

    dim3 grid(SS / TS, HH, BB * DSPLIT);   // 16 x 8 x 8 = 1024 CTAs
    dim3 block(NTHREADS);
    convspe_mma_kernel<<<grid, block, DYN_BYTES>>>(queries, keys, wq, wk, z, out);

    int n4 = OUTN / 4;
    convspe_combine_kernel<<<(n4 + 255) / 256, 256>>>(out);
}

// round 10
// speedup vs baseline: 1.4371x; 1.1185x over previous
#include <cuda_runtime.h>
#include <cstdint>

typedef uint32_t u32;

// Problem constants
#define BB 2
#define SS 1024
#define HH 8
#define DD 64
#define RR 32
#define KW 128
#define CC (HH*DD)          // 512
#define ZLEN (4*KW+SS)      // 1536
#define TS 64               // s per CTA
#define NTHREADS 128
#define DSPLIT 4            // d-reduction split across CTAs
#define DLOC (DD/DSPLIT)    // 16 d per CTA

#define OUTN (BB*SS*HH*RR*2)   // 1,048,576 floats (qhat+khat)

// partial sums for dh = 1..3
__device__ float g_part[3][OUTN];

// SMEM layout
#define ZSTRIDE 196                         // words/row (conflict-free, 16B-aligned)
#define Z_BYTES   (RR * ZSTRIDE * 4)        // 25088 per buffer
#define QKSTRIDE 132
#define QK_BYTES  (DLOC * QKSTRIDE * 4)     // 8448
#define W_BYTES   (2 * 256 * 4)             // 2048 per buffer (zero-padded filters)
#define DYN_BYTES (2*Z_BYTES + QK_BYTES + 2*W_BYTES)   // 62720

__device__ __forceinline__ u32 smem_u32(const void* p) {
    u32 a; asm("{ .reg .u64 t; cvta.to.shared.u64 t, %1; cvt.u32.u64 %0, t; }"
               : "=r"(a) : "l"(p));
    return a;
}
__device__ __forceinline__ void cpasync16(u32 dst, const void* src) {
    asm volatile("cp.async.cg.shared.global [%0], [%1], 16;" :: "r"(dst), "l"(src));
}
__device__ __forceinline__ void cpasync4(u32 dst, const void* src) {
    asm volatile("cp.async.ca.shared.global [%0], [%1], 4;" :: "r"(dst), "l"(src));
}
__device__ __forceinline__ void cp_commit() {
    asm volatile("cp.async.commit_group;" ::: "memory");
}
__device__ __forceinline__ void cp_wait_all() {
    asm volatile("cp.async.wait_group 0;" ::: "memory");
}

__device__ __forceinline__ u32 cvt_tf32(float x) {
    u32 r; asm("cvt.rna.tf32.f32 %0, %1;" : "=r"(r) : "f"(x)); return r;
}

__device__ __forceinline__ void mma_tf32(float* c,
                                         u32 a0, u32 a1, u32 a2, u32 a3,
                                         u32 b0, u32 b1) {
    asm volatile(
        "mma.sync.aligned.m16n8k8.row.col.f32.tf32.tf32.f32 "
        "{%0,%1,%2,%3}, {%4,%5,%6,%7}, {%8,%9}, {%0,%1,%2,%3};"
        : "+f"(c[0]), "+f"(c[1]), "+f"(c[2]), "+f"(c[3])
        : "r"(a0), "r"(a1), "r"(a2), "r"(a3), "r"(b0), "r"(b1));
}

struct PrefetchCtx {
    const float* zg;
    const float* wq;
    const float* wk;
    u32 zsu0, zsu1, wsu0, wsu1;
    int tid, b, s0, cbase;
};

__device__ __forceinline__ void prefetch_d(const PrefetchCtx& P, int dd) {
    const int c   = P.cbase + dd;
    const u32 zsu = (dd & 1) ? P.zsu1 : P.zsu0;
    const u32 wsu = (dd & 1) ? P.wsu1 : P.wsu0;
    #pragma unroll
    for (int i = 0; i < 12; i++) {
        int idx  = P.tid + i * NTHREADS;
        int zrow = idx / 48;
        int gq   = idx - zrow * 48;
        const float* src = P.zg + ((size_t)((P.b * RR + zrow) * CC + c)) * ZLEN
                         + KW + P.s0 + gq * 4;
        cpasync16(zsu + (u32)(zrow * ZSTRIDE + gq * 4) * 4u, src);
    }
    cpasync4(wsu + (64 + P.tid) * 4,       P.wk + c * KW + P.tid);
    cpasync4(wsu + (256 + 64 + P.tid) * 4, P.wq + c * KW + P.tid);
    cp_commit();
}

__global__ __launch_bounds__(NTHREADS, 3)
void convspe_mma_kernel(const float* __restrict__ qg,
                        const float* __restrict__ kg,
                        const float* __restrict__ wq,
                        const float* __restrict__ wk,
                        const float* __restrict__ zg,
                        float* __restrict__ out)
{
    extern __shared__ char dyn[];
    u32*   Zs0 = reinterpret_cast<u32*>(dyn);
    u32*   Zs1 = reinterpret_cast<u32*>(dyn + Z_BYTES);
    float* QK  = reinterpret_cast<float*>(dyn + 2 * Z_BYTES);
    float* W0  = reinterpret_cast<float*>(dyn + 2 * Z_BYTES + QK_BYTES);
    float* W1  = reinterpret_cast<float*>(dyn + 2 * Z_BYTES + QK_BYTES + W_BYTES);

    const int tid  = threadIdx.x;
    const int w    = tid >> 5;
    const int lane = tid & 31;
    const int g    = lane >> 2;       // row group 0..7
    const int qi   = lane & 3;        // quad index 0..3

    const int stile = blockIdx.x;     // 0..15
    const int h     = blockIdx.y;     // 0..7
    const int bz    = blockIdx.z;     // 0..7
    const int b     = bz >> 2;
    const int dh    = bz & 3;         // d-split index
    const int dbase = dh * DLOC;
    const int s0    = stile * TS;
    const int cbase = h * DD + dbase;

    // ---- zero-fill both W pads once (out-of-band entries stay 0 forever) ----
    #pragma unroll
    for (int i = 0; i < 4; i++) {
        W0[tid + i * NTHREADS] = 0.f;
        W1[tid + i * NTHREADS] = 0.f;
    }

    // ---- stage q/k transposed for this CTA's 16 d's: QK[dl][row] ----
    for (int idx = tid; idx < TS * 4; idx += NTHREADS) {  // 2 iters
        int srow = idx >> 2;
        int c4   = idx & 3;
        int goff = (((b * SS + s0 + srow) * HH + h) * DD) + dbase + c4 * 4;
        float4 q4 = *reinterpret_cast<const float4*>(qg + goff);
        float4 k4 = *reinterpret_cast<const float4*>(kg + goff);
        float qa[4] = {q4.x, q4.y, q4.z, q4.w};
        float ka[4] = {k4.x, k4.y, k4.z, k4.w};
        #pragma unroll
        for (int j = 0; j < 4; j++) {
            QK[(c4 * 4 + j) * QKSTRIDE + srow]      = qa[j];
            QK[(c4 * 4 + j) * QKSTRIDE + 64 + srow] = ka[j];
        }
    }

    PrefetchCtx P { zg, wq, wk,
                    smem_u32(Zs0), smem_u32(Zs1), smem_u32(W0), smem_u32(W1),
                    tid, b, s0, cbase };

    // ---- prefetch d = 0 ----
    prefetch_d(P, 0);

    // ---- per-warp constants: warp owns 2 m-tiles of one filter half ----
    const int f      = w >> 1;          // 0: qhat rows (filter wk), 1: khat rows (filter wq)
    const int c0     = (w & 1) * 4;     // chunk base
    const int m_base = w * 32;          // warp's first M row

    float acc[2][4][4];
    #pragma unroll
    for (int t = 0; t < 2; t++)
        #pragma unroll
        for (int n = 0; n < 4; n++)
            #pragma unroll
            for (int i = 0; i < 4; i++) acc[t][n][i] = 0.f;

    for (int d = 0; d < DLOC; d++) {
        cp_wait_all();        // this thread's cp.async group for d complete
        __syncthreads();      // data for d visible to all; buffer (d+1)&1 free

        if (d + 1 < DLOC) prefetch_d(P, d + 1);   // overlaps the MMA loop below

        const u32*   Zs = (d & 1) ? Zs1 : Zs0;
        const float* wp = ((d & 1) ? W1 : W0) + f * 256;

        // -- per-d A-row scalars --
        float qv00 = QK[d * QKSTRIDE + m_base + g];
        float qv01 = QK[d * QKSTRIDE + m_base + g + 8];
        float qv10 = QK[d * QKSTRIDE + m_base + 16 + g];
        float qv11 = QK[d * QKSTRIDE + m_base + 16 + g + 8];

        // -- 20 union chunks; m-tile0 active u<18, m-tile1 active u>=2 --
        #pragma unroll
        for (int u = 0; u < 20; u++) {
            const int kg = (c0 + u) * 8 + qi;

            u32 b0[4], b1[4];
            #pragma unroll
            for (int n = 0; n < 4; n++) {
                const u32* zr = Zs + (n * 8 + g) * ZSTRIDE + kg;
                b0[n] = zr[0];
                b1[n] = zr[4];
            }

            if (u < 18) {   // m-tile 0
                int wi = 64 + 8 * u + qi - g;
                u32 a0 = cvt_tf32(qv00 * wp[wi]);
                u32 a2 = cvt_tf32(qv00 * wp[wi + 4]);
                u32 a1 = cvt_tf32(qv01 * wp[wi - 8]);
                u32 a3 = cvt_tf32(qv01 * wp[wi - 4]);
                #pragma unroll
                for (int n = 0; n < 4; n++)
                    mma_tf32(acc[0][n], a0, a1, a2, a3, b0[n], b1[n]);
            }
            if (u >= 2) {   // m-tile 1
                int wi = 64 + 8 * u + qi - g - 16;
                u32 a0 = cvt_tf32(qv10 * wp[wi]);
                u32 a2 = cvt_tf32(qv10 * wp[wi + 4]);
                u32 a1 = cvt_tf32(qv11 * wp[wi - 8]);
                u32 a3 = cvt_tf32(qv11 * wp[wi - 4]);
                #pragma unroll
                for (int n = 0; n < 4; n++)
                    mma_tf32(acc[1][n], a0, a1, a2, a3, b0[n], b1[n]);
            }
        }

        __syncthreads();   // all consumers of buffer d done before its refill at d+2
    }

    // ---- epilogue: dh==0 writes out directly, others write partial scratch ----
    float* obase0 = (dh == 0) ? out : g_part[dh - 1];
    const int khat_off = BB * SS * HH * RR;
    #pragma unroll
    for (int t = 0; t < 2; t++) {
        int row  = m_base + 16 * t + g;
        int srow = row & 63;
        float* ob  = obase0 + (f ? khat_off : 0)
                   + ((b * SS + s0 + srow) * HH + h) * RR;
        float* ob8 = ob + 8 * HH * RR;  // srow + 8
        #pragma unroll
        for (int n = 0; n < 4; n++) {
            int col = n * 8 + 2 * qi;
            *reinterpret_cast<float2*>(ob  + col) = make_float2(acc[t][n][0], acc[t][n][1]);
            *reinterpret_cast<float2*>(ob8 + col) = make_float2(acc[t][n][2], acc[t][n][3]);
        }
    }
}

// deterministic combine: out += part0 + part1 + part2
__global__ __launch_bounds__(256)
void convspe_combine_kernel(float* __restrict__ out)
{
    int i = blockIdx.x * blockDim.x + threadIdx.x;   // float4 index
    if (i >= OUTN / 4) return;
    float4 o  = reinterpret_cast<float4*>(out)[i];
    float4 p0 = reinterpret_cast<const float4*>(g_part[0])[i];
    float4 p1 = reinterpret_cast<const float4*>(g_part[1])[i];
    float4 p2 = reinterpret_cast<const float4*>(g_part[2])[i];
    o.x += p0.x + p1.x + p2.x;
    o.y += p0.y + p1.y + p2.y;
    o.z += p0.z + p1.z + p2.z;
    o.w += p0.w + p1.w + p2.w;
    reinterpret_cast<float4*>(out)[i] = o;
}

extern "C" void kernel_launch(void* const* d_in, const int* in_sizes, int n_in,
                              void* d_out, int out_size)
{
    const float* queries = (const float*)d_in[0];
    const float* keys    = (const float*)d_in[1];
    const float* wq      = (const float*)d_in[2];
    const float* wk      = (const float*)d_in[3];
    const float* z       = (const float*)d_in[4];
    float* out = (float*)d_out;

    cudaFuncSetAttribute(convspe_mma_kernel,
                         cudaFuncAttributeMaxDynamicSharedMemorySize, DYN_BYTES);

    dim3 grid(SS / TS, HH, BB * DSPLIT);   // 16 x 8 x 8 = 1024 CTAs
    dim3 block(NTHREADS);
    convspe_mma_kernel<<<grid, block, DYN_BYTES>>>(queries, keys, wq, wk, z, out);

    int n4 = OUTN / 4;
    convspe_combine_kernel<<<(n4 + 255) / 256, 256>>>(out);
}

// round 11
// speedup vs baseline: 1.5359x; 1.0688x over previous
#include <cuda_runtime.h>
#include <cstdint>

typedef uint32_t u32;

// Problem constants
#define BB 2
#define SS 1024
#define HH 8
#define DD 64
#define RR 32
#define KW 128
#define CC (HH*DD)          // 512
#define ZLEN (4*KW+SS)      // 1536
#define TS 64               // s per CTA
#define NTHREADS 128
#define DSPLIT 4            // d-reduction split across CTAs
#define DLOC (DD/DSPLIT)    // 16 d per CTA

#define OUTN (BB*SS*HH*RR*2)   // 1,048,576 floats (qhat+khat)

// partial sums for dh = 1..3
__device__ float g_part[3][OUTN];

// SMEM layout
#define ZSTRIDE 196                         // words/row (conflict-free, 16B-aligned)
#define Z_BYTES   (RR * ZSTRIDE * 4)        // 25088 per buffer
#define QKSTRIDE 132
#define QK_BYTES  (DLOC * QKSTRIDE * 4)     // 8448
#define W_BYTES   (2 * 256 * 4)             // 2048 per buffer (zero-padded filters)
#define DYN_BYTES (2*Z_BYTES + QK_BYTES + 2*W_BYTES)   // 62720

__device__ __forceinline__ u32 smem_u32(const void* p) {
    u32 a; asm("{ .reg .u64 t; cvta.to.shared.u64 t, %1; cvt.u32.u64 %0, t; }"
               : "=r"(a) : "l"(p));
    return a;
}
__device__ __forceinline__ void cpasync16(u32 dst, const void* src) {
    asm volatile("cp.async.cg.shared.global [%0], [%1], 16;" :: "r"(dst), "l"(src));
}
__device__ __forceinline__ void cpasync4(u32 dst, const void* src) {
    asm volatile("cp.async.ca.shared.global [%0], [%1], 4;" :: "r"(dst), "l"(src));
}
__device__ __forceinline__ void cp_commit() {
    asm volatile("cp.async.commit_group;" ::: "memory");
}
__device__ __forceinline__ void cp_wait_all() {
    asm volatile("cp.async.wait_group 0;" ::: "memory");
}

__device__ __forceinline__ u32 cvt_tf32(float x) {
    u32 r; asm("cvt.rna.tf32.f32 %0, %1;" : "=r"(r) : "f"(x)); return r;
}

__device__ __forceinline__ void mma_acc(float* c,
                                        u32 a0, u32 a1, u32 a2, u32 a3,
                                        u32 b0, u32 b1) {
    asm volatile(
        "mma.sync.aligned.m16n8k8.row.col.f32.tf32.tf32.f32 "
        "{%0,%1,%2,%3}, {%4,%5,%6,%7}, {%8,%9}, {%0,%1,%2,%3};"
        : "+f"(c[0]), "+f"(c[1]), "+f"(c[2]), "+f"(c[3])
        : "r"(a0), "r"(a1), "r"(a2), "r"(a3), "r"(b0), "r"(b1));
}
__device__ __forceinline__ void mma_init(float* c,
                                         u32 a0, u32 a1, u32 a2, u32 a3,
                                         u32 b0, u32 b1) {
    asm volatile(
        "mma.sync.aligned.m16n8k8.row.col.f32.tf32.tf32.f32 "
        "{%0,%1,%2,%3}, {%4,%5,%6,%7}, {%8,%9}, {%10,%11,%12,%13};"
        : "=f"(c[0]), "=f"(c[1]), "=f"(c[2]), "=f"(c[3])
        : "r"(a0), "r"(a1), "r"(a2), "r"(a3), "r"(b0), "r"(b1),
          "f"(0.f), "f"(0.f), "f"(0.f), "f"(0.f));
}

struct PrefetchCtx {
    const float* zg;
    const float* wq;
    const float* wk;
    u32 zsu0, zsu1, wsu0, wsu1;
    int tid, b, s0, cbase;
};

__device__ __forceinline__ void prefetch_d(const PrefetchCtx& P, int dd) {
    const int c   = P.cbase + dd;
    const u32 zsu = (dd & 1) ? P.zsu1 : P.zsu0;
    const u32 wsu = (dd & 1) ? P.wsu1 : P.wsu0;
    #pragma unroll
    for (int i = 0; i < 12; i++) {
        int idx  = P.tid + i * NTHREADS;
        int zrow = idx / 48;
        int gq   = idx - zrow * 48;
        const float* src = P.zg + ((size_t)((P.b * RR + zrow) * CC + c)) * ZLEN
                         + KW + P.s0 + gq * 4;
        cpasync16(zsu + (u32)(zrow * ZSTRIDE + gq * 4) * 4u, src);
    }
    cpasync4(wsu + (64 + P.tid) * 4,       P.wk + c * KW + P.tid);
    cpasync4(wsu + (256 + 64 + P.tid) * 4, P.wq + c * KW + P.tid);
    cp_commit();
}

__global__ __launch_bounds__(NTHREADS, 3)
void convspe_mma_kernel(const float* __restrict__ qg,
                        const float* __restrict__ kg,
                        const float* __restrict__ wq,
                        const float* __restrict__ wk,
                        const float* __restrict__ zg,
                        float* __restrict__ out)
{
    extern __shared__ char dyn[];
    u32*   Zs0 = reinterpret_cast<u32*>(dyn);
    u32*   Zs1 = reinterpret_cast<u32*>(dyn + Z_BYTES);
    float* QK  = reinterpret_cast<float*>(dyn + 2 * Z_BYTES);
    float* W0  = reinterpret_cast<float*>(dyn + 2 * Z_BYTES + QK_BYTES);
    float* W1  = reinterpret_cast<float*>(dyn + 2 * Z_BYTES + QK_BYTES + W_BYTES);

    const int tid  = threadIdx.x;
    const int w    = tid >> 5;
    const int lane = tid & 31;
    const int g    = lane >> 2;       // row group 0..7
    const int qi   = lane & 3;        // quad index 0..3

    const int stile = blockIdx.x;     // 0..15
    const int h     = blockIdx.y;     // 0..7
    const int bz    = blockIdx.z;     // 0..7
    const int b     = bz >> 2;
    const int dh    = bz & 3;         // d-split index
    const int dbase = dh * DLOC;
    const int s0    = stile * TS;
    const int cbase = h * DD + dbase;

    // ---- zero-fill both W pads once (out-of-band entries stay 0 forever) ----
    #pragma unroll
    for (int i = 0; i < 4; i++) {
        W0[tid + i * NTHREADS] = 0.f;
        W1[tid + i * NTHREADS] = 0.f;
    }

    // ---- stage q/k transposed for this CTA's 16 d's: QK[dl][row] ----
    for (int idx = tid; idx < TS * 4; idx += NTHREADS) {  // 2 iters
        int srow = idx >> 2;
        int c4   = idx & 3;
        int goff = (((b * SS + s0 + srow) * HH + h) * DD) + dbase + c4 * 4;
        float4 q4 = *reinterpret_cast<const float4*>(qg + goff);
        float4 k4 = *reinterpret_cast<const float4*>(kg + goff);
        float qa[4] = {q4.x, q4.y, q4.z, q4.w};
        float ka[4] = {k4.x, k4.y, k4.z, k4.w};
        #pragma unroll
        for (int j = 0; j < 4; j++) {
            QK[(c4 * 4 + j) * QKSTRIDE + srow]      = qa[j];
            QK[(c4 * 4 + j) * QKSTRIDE + 64 + srow] = ka[j];
        }
    }

    PrefetchCtx P { zg, wq, wk,
                    smem_u32(Zs0), smem_u32(Zs1), smem_u32(W0), smem_u32(W1),
                    tid, b, s0, cbase };

    // ---- prefetch d = 0 ----
    prefetch_d(P, 0);

    // ---- per-warp constants: warp owns 2 m-tiles of one filter half ----
    const int f      = w >> 1;          // 0: qhat rows (filter wk), 1: khat rows (filter wq)
    const int c0     = (w & 1) * 4;     // chunk base
    const int fbase  = f * 64 + (w & 1) * 32;
    const int qg_off = qi - g;          // lane band offset

    float acc0[4][4], acc1[4][4];       // running d-sums for m-tile0 / m-tile1
    #pragma unroll
    for (int n = 0; n < 4; n++)
        #pragma unroll
        for (int i = 0; i < 4; i++) { acc0[n][i] = 0.f; acc1[n][i] = 0.f; }

    for (int d = 0; d < DLOC; d++) {
        cp_wait_all();        // this thread's cp.async group for d complete
        __syncthreads();      // data for d visible; iteration d-1 consumers done
                              // (this barrier also protects the refill below)

        if (d + 1 < DLOC) prefetch_d(P, d + 1);   // overlaps the MMA loop below

        const u32*   Zs = (d & 1) ? Zs1 : Zs0;
        const float* wp = ((d & 1) ? W1 : W0) + f * 256;

        // -- build unscaled A frags (shared by both m-tiles, R8-verified mapping) --
        u32 aw0[21], aw2[21];
        #pragma unroll
        for (int i = 0; i < 21; i++) {
            aw0[i] = cvt_tf32(wp[40 + 8 * i + qg_off]);
            aw2[i] = cvt_tf32(wp[44 + 8 * i + qg_off]);
        }

        // -- per-d conv via MMA: work = W_band x Z (no q scaling) --
        float work0[4][4], work1[4][4];

        #pragma unroll
        for (int u = 0; u < 20; u++) {
            const int kg = (c0 + u) * 8 + qi;
            u32 b0[4], b1[4];
            #pragma unroll
            for (int n = 0; n < 4; n++) {
                const u32* zr = Zs + (n * 8 + g) * ZSTRIDE + kg;
                b0[n] = zr[0];
                b1[n] = zr[4];
            }

            if (u < 18) {   // m-tile 0: local chunk u
                const u32 a0 = aw0[u + 3], a1 = aw0[u + 2];
                const u32 a2 = aw2[u + 3], a3 = aw2[u + 2];
                if (u == 0) {
                    #pragma unroll
                    for (int n = 0; n < 4; n++)
                        mma_init(work0[n], a0, a1, a2, a3, b0[n], b1[n]);
                } else {
                    #pragma unroll
                    for (int n = 0; n < 4; n++)
                        mma_acc(work0[n], a0, a1, a2, a3, b0[n], b1[n]);
                }
            }
            if (u >= 2) {   // m-tile 1: frags shifted by 2 chunks
                const u32 a0 = aw0[u + 1], a1 = aw0[u];
                const u32 a2 = aw2[u + 1], a3 = aw2[u];
                if (u == 2) {
                    #pragma unroll
                    for (int n = 0; n < 4; n++)
                        mma_init(work1[n], a0, a1, a2, a3, b0[n], b1[n]);
                } else {
                    #pragma unroll
                    for (int n = 0; n < 4; n++)
                        mma_acc(work1[n], a0, a1, a2, a3, b0[n], b1[n]);
                }
            }
        }

        // -- scale by q/k at (s, d) and accumulate over d (exact fp32) --
        const float* qkrow = QK + d * QKSTRIDE + fbase;
        const float qv00 = qkrow[g];
        const float qv01 = qkrow[g + 8];
        const float qv10 = qkrow[g + 16];
        const float qv11 = qkrow[g + 24];
        #pragma unroll
        for (int n = 0; n < 4; n++) {
            acc0[n][0] = fmaf(qv00, work0[n][0], acc0[n][0]);
            acc0[n][1] = fmaf(qv00, work0[n][1], acc0[n][1]);
            acc0[n][2] = fmaf(qv01, work0[n][2], acc0[n][2]);
            acc0[n][3] = fmaf(qv01, work0[n][3], acc0[n][3]);
            acc1[n][0] = fmaf(qv10, work1[n][0], acc1[n][0]);
            acc1[n][1] = fmaf(qv10, work1[n][1], acc1[n][1]);
            acc1[n][2] = fmaf(qv11, work1[n][2], acc1[n][2]);
            acc1[n][3] = fmaf(qv11, work1[n][3], acc1[n][3]);
        }
        // no trailing __syncthreads: the top-of-loop barrier at d+1 orders
        // this iteration's smem reads against the buffer refill at d+2
    }

    // ---- epilogue: dh==0 writes out directly, others write partial scratch ----
    float* obase0 = (dh == 0) ? out : g_part[dh - 1];
    const int khat_off = BB * SS * HH * RR;
    #pragma unroll
    for (int mt = 0; mt < 2; mt++) {
        const int srow = (w & 1) * 32 + mt * 16 + g;
        float* ob  = obase0 + (f ? khat_off : 0)
                   + ((b * SS + s0 + srow) * HH + h) * RR;
        float* ob8 = ob + 8 * HH * RR;     // srow + 8
        #pragma unroll
        for (int n = 0; n < 4; n++) {
            const int col = n * 8 + 2 * qi;
            const float (*acc)[4] = mt ? acc1 : acc0;
            *reinterpret_cast<float2*>(ob  + col) = make_float2(acc[n][0], acc[n][1]);
            *reinterpret_cast<float2*>(ob8 + col) = make_float2(acc[n][2], acc[n][3]);
        }
    }
}

// deterministic combine: out += part0 + part1 + part2
__global__ __launch_bounds__(256)
void convspe_combine_kernel(float* __restrict__ out)
{
    int i = blockIdx.x * blockDim.x + threadIdx.x;   // float4 index
    if (i >= OUTN / 4) return;
    float4 o  = reinterpret_cast<float4*>(out)[i];
    float4 p0 = reinterpret_cast<const float4*>(g_part[0])[i];
    float4 p1 = reinterpret_cast<const float4*>(g_part[1])[i];
    float4 p2 = reinterpret_cast<const float4*>(g_part[2])[i];
    o.x += p0.x + p1.x + p2.x;
    o.y += p0.y + p1.y + p2.y;
    o.z += p0.z + p1.z + p2.z;
    o.w += p0.w + p1.w + p2.w;
    reinterpret_cast<float4*>(out)[i] = o;
}

extern "C" void kernel_launch(void* const* d_in, const int* in_sizes, int n_in,
                              void* d_out, int out_size)
{
    const float* queries = (const float*)d_in[0];
    const float* keys    = (const float*)d_in[1];
    const float* wq      = (const float*)d_in[2];
    const float* wk      = (const float*)d_in[3];
    const float* z       = (const float*)d_in[4];
    float* out = (float*)d_out;

    cudaFuncSetAttribute(convspe_mma_kernel,
                         cudaFuncAttributeMaxDynamicSharedMemorySize, DYN_BYTES);

    dim3 grid(SS / TS, HH, BB * DSPLIT);   // 16 x 8 x 8 = 1024 CTAs
    dim3 block(NTHREADS);
    convspe_mma_kernel<<<grid, block, DYN_BYTES>>>(queries, keys, wq, wk, z, out);

    int n4 = OUTN / 4;
    convspe_combine_kernel<<<(n4 + 255) / 256, 256>>>(out);
}